// round 2
// baseline (speedup 1.0000x reference)
#include <cuda_runtime.h>

#define B_ 2
#define V_ 20000
#define C_ 32
#define NB_ 12
#define KS_ 9
#define OUT_ 32
#define NNODES (B_*V_)
#define KDIM (KS_*C_)     /* 288 */
#define WSTRIDE 290       /* padded smem stride for transposed W (bank-conflict-free) */

// Scratch (module-allocated, no runtime allocation)
__device__ float g_ux[NNODES * KS_];   // 1.44 MB, L2-resident

// packed fp32x2 FMA: d = a*b + d  (both lanes independent)
#define FMA_F32X2(d, a, b) \
    asm("fma.rn.f32x2 %0, %1, %2, %0;" : "+l"(d) : "l"(a), "l"(b))

__device__ __forceinline__ float hsum_f32x2(unsigned long long v) {
    float lo, hi;
    asm("mov.b64 {%0,%1}, %2;" : "=f"(lo), "=f"(hi) : "l"(v));
    return lo + hi;
}

// ---------------------------------------------------------------------------
// Kernel 1: ux[node][k] = sum_c x[node][c] * u[c][k]
// 4 threads per node (8 channels each), butterfly shuffle reduce.
// ---------------------------------------------------------------------------
__global__ void __launch_bounds__(512) k_ux(const float* __restrict__ x,
                                            const float* __restrict__ u) {
    __shared__ float u_sm[C_ * KS_];
    for (int i = threadIdx.x; i < C_ * KS_; i += 512) u_sm[i] = u[i];
    __syncthreads();

    int t = blockIdx.x * 512 + threadIdx.x;
    int node = t >> 2;
    int qq = t & 3;
    bool valid = node < NNODES;
    int nc = valid ? node : (NNODES - 1);

    const float4* xr = reinterpret_cast<const float4*>(x + (size_t)nc * C_) + qq * 2;
    float4 v0 = xr[0];
    float4 v1 = xr[1];
    float xs[8] = {v0.x, v0.y, v0.z, v0.w, v1.x, v1.y, v1.z, v1.w};

    float acc[KS_];
#pragma unroll
    for (int k = 0; k < KS_; k++) acc[k] = 0.f;

    const int cbase = qq * 8;
#pragma unroll
    for (int j = 0; j < 8; j++) {
#pragma unroll
        for (int k = 0; k < KS_; k++)
            acc[k] = fmaf(xs[j], u_sm[(cbase + j) * KS_ + k], acc[k]);
    }
#pragma unroll
    for (int k = 0; k < KS_; k++) acc[k] += __shfl_xor_sync(0xffffffffu, acc[k], 1);
#pragma unroll
    for (int k = 0; k < KS_; k++) acc[k] += __shfl_xor_sync(0xffffffffu, acc[k], 2);

    if (valid && qq == 0) {
        float* o = g_ux + (size_t)node * KS_;
#pragma unroll
        for (int k = 0; k < KS_; k++) o[k] = acc[k];
    }
}

// ---------------------------------------------------------------------------
// Kernel 2 (fused): per 64-node tile
//   phase A: per-node softmax attention + neighbor aggregation -> y_sm[64][288]
//            (q staged transiently in the warp's own y_sm row)
//   phase B: GEMM  out[64][32] = relu(y_sm @ W2t + b), packed f32x2 FMAs,
//            W transposed in smem [o][k*32+c], stride 290.
// ---------------------------------------------------------------------------
#define M_TILE 64
#define THREADS_F 512

__global__ void __launch_bounds__(THREADS_F, 2)
k_fused(const float* __restrict__ x, const float* __restrict__ W,
        const float* __restrict__ cvec, const float* __restrict__ bias,
        const int* __restrict__ adj, float* __restrict__ out) {
    extern __shared__ float smem[];
    float* w_sm = smem;                      // OUT_ * WSTRIDE = 9280 floats
    float* y_sm = smem + OUT_ * WSTRIDE;     // M_TILE * KDIM  = 18432 floats
    __shared__ float c_sm[KS_];

    const int tid = threadIdx.x;

    // Load W transposed: w_sm[o*WSTRIDE + (k*32+c)] = W[c*288 + k*32 + o]
    for (int idx = tid; idx < KDIM * OUT_; idx += THREADS_F) {
        int o = idx & 31;
        int i = idx >> 5;       // i = k*32+c
        int c = i & 31;
        int k = i >> 5;
        w_sm[o * WSTRIDE + i] = W[c * KDIM + k * OUT_ + o];
    }
    if (tid < KS_) c_sm[tid] = cvec[tid];
    __syncthreads();

    const int warp = tid >> 5;
    const int lane = tid & 31;
    const int row0 = blockIdx.x * M_TILE;

    // ---- attention phase: each warp handles 4 nodes ----
    for (int it = 0; it < 4; it++) {
        const int l = warp * 4 + it;
        const int node = row0 + l;
        const int b = node / V_;
        const int v = node - b * V_;

        int a = (lane < NB_) ? adj[v * NB_ + lane] : 0;
        unsigned nz = __ballot_sync(0xffffffffu, a != 0);
        int deg = __popc(nz);
        float inv_deg = deg ? (1.f / (float)deg) : 0.f;

        const float* uxs = g_ux + (size_t)node * KS_;
        float* q = &y_sm[l * KDIM];   // transient overlay, consumed before y store

        // 108 softmax logits/exps spread over lanes
#pragma unroll
        for (int j = 0; j < 4; j++) {
            int p = lane + 32 * j;
            int n = p / KS_;
            int k = p - n * KS_;
            int an = __shfl_sync(0xffffffffu, a, n & 31);
            if (p < NB_ * KS_) {
                float e = 0.f;
                if (an) {
                    float un = g_ux[((size_t)b * V_ + (an - 1)) * KS_ + k];
                    e = __expf(uxs[k] - un + c_sm[k]);
                }
                q[p] = e;
            }
        }
        __syncwarp();

        // row-normalize, fold inv_deg
        if (lane < NB_) {
            float s = 0.f;
#pragma unroll
            for (int k = 0; k < KS_; k++) s += q[lane * KS_ + k];
            float sc = (a && s > 0.f) ? (inv_deg / s) : 0.f;
#pragma unroll
            for (int k = 0; k < KS_; k++) q[lane * KS_ + k] *= sc;
        }
        __syncwarp();

        // lane = channel c; accumulate y[k] over neighbors
        float y[KS_];
#pragma unroll
        for (int k = 0; k < KS_; k++) y[k] = 0.f;

#pragma unroll
        for (int n = 0; n < NB_; n++) {
            int an = __shfl_sync(0xffffffffu, a, n);
            if (an == 0) continue;   // warp-uniform
            float xv = x[((size_t)b * V_ + (an - 1)) * C_ + lane];  // 128B coalesced
#pragma unroll
            for (int k = 0; k < KS_; k++)
                y[k] = fmaf(q[n * KS_ + k], xv, y[k]);
        }
        __syncwarp();   // all lanes done reading q before overwrite

#pragma unroll
        for (int k = 0; k < KS_; k++)
            y_sm[l * KDIM + k * 32 + lane] = y[k];
    }
    __syncthreads();

    // ---- GEMM phase: 2 rows x 2 cols per thread, packed f32x2 over k ----
    const int tr2 = (tid >> 4) * 2;   // 0..62
    const int tc = tid & 15;          // cols {tc, tc+16}

    unsigned long long acc00 = 0ull, acc01 = 0ull, acc10 = 0ull, acc11 = 0ull;

    const unsigned long long* y0 =
        reinterpret_cast<const unsigned long long*>(&y_sm[tr2 * KDIM]);
    const unsigned long long* y1 =
        reinterpret_cast<const unsigned long long*>(&y_sm[(tr2 + 1) * KDIM]);
    const unsigned long long* w0 =
        reinterpret_cast<const unsigned long long*>(&w_sm[tc * WSTRIDE]);
    const unsigned long long* w1 =
        reinterpret_cast<const unsigned long long*>(&w_sm[(tc + 16) * WSTRIDE]);

#pragma unroll 8
    for (int kk = 0; kk < KDIM / 2; kk++) {
        unsigned long long ya = y0[kk];
        unsigned long long yb = y1[kk];
        unsigned long long wa = w0[kk];
        unsigned long long wb = w1[kk];
        FMA_F32X2(acc00, ya, wa);
        FMA_F32X2(acc01, ya, wb);
        FMA_F32X2(acc10, yb, wa);
        FMA_F32X2(acc11, yb, wb);
    }

    float r00 = hsum_f32x2(acc00);
    float r01 = hsum_f32x2(acc01);
    float r10 = hsum_f32x2(acc10);
    float r11 = hsum_f32x2(acc11);

    const float b0 = bias[tc];
    const float b1 = bias[tc + 16];
    const size_t r = (size_t)(row0 + tr2);
    out[r * OUT_ + tc]            = fmaxf(r00 + b0, 0.f);
    out[r * OUT_ + tc + 16]       = fmaxf(r01 + b1, 0.f);
    out[(r + 1) * OUT_ + tc]      = fmaxf(r10 + b0, 0.f);
    out[(r + 1) * OUT_ + tc + 16] = fmaxf(r11 + b1, 0.f);
}

// ---------------------------------------------------------------------------
// Inputs (metadata order): x, W, u, c, b, adj
// ---------------------------------------------------------------------------
extern "C" void kernel_launch(void* const* d_in, const int* in_sizes, int n_in,
                              void* d_out, int out_size) {
    const float* x    = (const float*)d_in[0];
    const float* W    = (const float*)d_in[1];
    const float* u    = (const float*)d_in[2];
    const float* cvec = (const float*)d_in[3];
    const float* bias = (const float*)d_in[4];
    const int*   adj  = (const int*)d_in[5];
    float* out = (float*)d_out;

    const int smem_f = (OUT_ * WSTRIDE + M_TILE * KDIM) * (int)sizeof(float); // 110848
    cudaFuncSetAttribute(k_fused, cudaFuncAttributeMaxDynamicSharedMemorySize, smem_f);

    k_ux<<<(NNODES * 4 + 511) / 512, 512>>>(x, u);
    k_fused<<<NNODES / M_TILE, THREADS_F, smem_f>>>(x, W, cvec, bias, adj, out);
}

// round 3
// speedup vs baseline: 1.0669x; 1.0669x over previous
#include <cuda_runtime.h>

#define B_ 2
#define V_ 20000
#define C_ 32
#define NB_ 12
#define KS_ 9
#define OUT_ 32
#define NNODES (B_*V_)
#define KDIM (KS_*C_)     /* 288 */

typedef unsigned long long u64;

// Scratch (module-allocated)
__device__ float g_ep[NNODES * 12];              // exp(ux+c), padded to 12 (pads=0)
__device__ float g_em[NNODES * 12];              // exp(-ux),  padded to 12 (pads=0)
__device__ float g_y[(size_t)NNODES * KDIM];     // 46 MB (L2-transient)

#define FMA_F32X2(d, a, b) \
    asm("fma.rn.f32x2 %0, %1, %2, %0;" : "+l"(d) : "l"(a), "l"(b))

__device__ __forceinline__ u64 pack2(float a, float b) {
    u64 r; asm("mov.b64 %0, {%1,%2};" : "=l"(r) : "f"(a), "f"(b)); return r;
}
__device__ __forceinline__ float lo32(u64 v) {
    float a, b; asm("mov.b64 {%0,%1}, %2;" : "=f"(a), "=f"(b) : "l"(v)); return a;
}
__device__ __forceinline__ float hi32(u64 v) {
    float a, b; asm("mov.b64 {%0,%1}, %2;" : "=f"(a), "=f"(b) : "l"(v)); return b;
}
__device__ __forceinline__ float hsum(u64 v) { return lo32(v) + hi32(v); }

// ---------------------------------------------------------------------------
// Kernel 1: ux = x.u ; store E+[k]=exp(ux+c), E-[k]=exp(-ux), 12-padded.
// 4 threads per node, butterfly reduce.
// ---------------------------------------------------------------------------
__global__ void __launch_bounds__(512) k_ux(const float* __restrict__ x,
                                            const float* __restrict__ u,
                                            const float* __restrict__ cvec) {
    __shared__ float u_sm[C_ * KS_];
    __shared__ float c_sm[KS_];
    for (int i = threadIdx.x; i < C_ * KS_; i += 512) u_sm[i] = u[i];
    if (threadIdx.x < KS_) c_sm[threadIdx.x] = cvec[threadIdx.x];
    __syncthreads();

    int t = blockIdx.x * 512 + threadIdx.x;
    int node = t >> 2;
    int qq = t & 3;
    bool valid = node < NNODES;
    int nc = valid ? node : (NNODES - 1);

    const float4* xr = reinterpret_cast<const float4*>(x + (size_t)nc * C_) + qq * 2;
    float4 v0 = xr[0];
    float4 v1 = xr[1];
    float xs[8] = {v0.x, v0.y, v0.z, v0.w, v1.x, v1.y, v1.z, v1.w};

    float acc[KS_];
#pragma unroll
    for (int k = 0; k < KS_; k++) acc[k] = 0.f;
    const int cbase = qq * 8;
#pragma unroll
    for (int j = 0; j < 8; j++)
#pragma unroll
        for (int k = 0; k < KS_; k++)
            acc[k] = fmaf(xs[j], u_sm[(cbase + j) * KS_ + k], acc[k]);
#pragma unroll
    for (int k = 0; k < KS_; k++) acc[k] += __shfl_xor_sync(0xffffffffu, acc[k], 1);
#pragma unroll
    for (int k = 0; k < KS_; k++) acc[k] += __shfl_xor_sync(0xffffffffu, acc[k], 2);

    if (valid) {
        float* ep = g_ep + (size_t)node * 12;
        float* em = g_em + (size_t)node * 12;
#pragma unroll
        for (int k = qq; k < KS_; k += 4) {
            ep[k] = __expf(acc[k] + c_sm[k]);
            em[k] = __expf(-acc[k]);
        }
        if (qq > 0) {           // zero pads k = 9,10,11
            ep[8 + qq] = 0.f;
            em[8 + qq] = 0.f;
        }
    }
}

// ---------------------------------------------------------------------------
// Kernel 2: exp-free attention + neighbor aggregation -> g_y[node][288]
// Warp per node. q[n][k] = E+self[k]*E-nb[k], normalized, inv_deg folded.
// ---------------------------------------------------------------------------
__global__ void __launch_bounds__(256) k_attn(const float* __restrict__ x,
                                              const int* __restrict__ adj) {
    __shared__ float q_sm[8][NB_ * 12];   // 12 floats per neighbor (pads at 9..11)
    const int warp = threadIdx.x >> 5;
    const int lane = threadIdx.x & 31;
    const int node = blockIdx.x * 8 + warp;   // grid = 5000 exact
    const int b = node / V_;
    const int v = node - b * V_;

    int a = (lane < NB_) ? adj[v * NB_ + lane] : 0;
    unsigned nz = __ballot_sync(0xffffffffu, a != 0);
    int deg = __popc(nz);
    float inv_deg = deg ? (1.f / (float)deg) : 0.f;

    if (a) {
        const float4* em4 = reinterpret_cast<const float4*>(
            g_em + (size_t)(b * V_ + (a - 1)) * 12);
        const float4* ep4 = reinterpret_cast<const float4*>(
            g_ep + (size_t)node * 12);
        float4 m0 = em4[0], m1 = em4[1], m2 = em4[2];
        float4 p0 = ep4[0], p1 = ep4[1], p2 = ep4[2];
        float q0 = p0.x * m0.x, q1 = p0.y * m0.y, q2 = p0.z * m0.z, q3 = p0.w * m0.w;
        float q4 = p1.x * m1.x, q5 = p1.y * m1.y, q6 = p1.z * m1.z, q7 = p1.w * m1.w;
        float q8 = p2.x * m2.x;   // pads are 0*0
        float s = q0 + q1 + q2 + q3 + q4 + q5 + q6 + q7 + q8;
        float sc = inv_deg / s;
        float4* qr = reinterpret_cast<float4*>(&q_sm[warp][lane * 12]);
        qr[0] = make_float4(q0 * sc, q1 * sc, q2 * sc, q3 * sc);
        qr[1] = make_float4(q4 * sc, q5 * sc, q6 * sc, q7 * sc);
        qr[2] = make_float4(q8 * sc, 0.f, 0.f, 0.f);
    }
    __syncwarp();

    // aggregation: lane = channel; 5 packed f32x2 accumulators over k-pairs
    u64 acc[5];
#pragma unroll
    for (int t = 0; t < 5; t++) acc[t] = 0ull;

#pragma unroll
    for (int n = 0; n < NB_; n++) {
        int an = __shfl_sync(0xffffffffu, a, n);
        if (an == 0) continue;   // warp-uniform
        float xv = x[((size_t)b * V_ + (an - 1)) * C_ + lane];
        u64 xx = pack2(xv, xv);
        const u64* q64 = reinterpret_cast<const u64*>(&q_sm[warp][n * 12]);
#pragma unroll
        for (int t = 0; t < 5; t++) FMA_F32X2(acc[t], q64[t], xx);
    }

    float* yo = g_y + (size_t)node * KDIM;
#pragma unroll
    for (int t = 0; t < 4; t++) {
        yo[(2 * t) * C_ + lane] = lo32(acc[t]);
        yo[(2 * t + 1) * C_ + lane] = hi32(acc[t]);
    }
    yo[8 * C_ + lane] = lo32(acc[4]);
}

// ---------------------------------------------------------------------------
// Kernel 3: out = relu(Y @ W2 + b). M=40000, K=288, N=32.
// 64 threads, M_TILE=128, 8x8 microtile, f32x2 FMAs, XOR-swizzled smem.
// ---------------------------------------------------------------------------
#define MT 128
#define KC 16
__global__ void __launch_bounds__(64) k_gemm(const float* __restrict__ W,
                                             const float* __restrict__ bias,
                                             const float* __restrict__ Y,
                                             float* __restrict__ out) {
    __shared__ __align__(16) float w_sm[OUT_ * KDIM];   // [o][k] swizzled, 36 KB
    __shared__ __align__(16) float y_sm[MT * KC];       // [row][k] swizzled, 8 KB

    const int tid = threadIdx.x;
    const int rg = tid >> 2;   // 0..15 (8 rows each)
    const int cg = tid & 3;    // 0..3  (8 cols each)

    // Stage W: w_sm[o][i] = W2[i][o] = W[(i&31)*288 + (i>>5)*32 + o], pair-swizzled
    for (int o = 0; o < OUT_; o++) {
        for (int i = tid; i < KDIM; i += 64) {
            int p = i >> 1, lo = i & 1;
            w_sm[o * KDIM + 2 * (p ^ (o >> 3)) + lo] =
                W[(i & 31) * KDIM + (i >> 5) * OUT_ + o];
        }
    }

    const int row0 = blockIdx.x * MT;
    const int r0 = tid, r1 = tid + 64;   // staged rows

    u64 acc[64];
#pragma unroll
    for (int i = 0; i < 64; i++) acc[i] = 0ull;

    float4 pre[2][4];
    // prefetch chunk 0
#pragma unroll
    for (int rr = 0; rr < 2; rr++) {
        int grow = row0 + (rr ? r1 : r0);
        if (grow < NNODES) {
            const float4* src = reinterpret_cast<const float4*>(Y + (size_t)grow * KDIM);
#pragma unroll
            for (int j = 0; j < 4; j++) pre[rr][j] = src[j];
        } else {
#pragma unroll
            for (int j = 0; j < 4; j++) pre[rr][j] = make_float4(0, 0, 0, 0);
        }
    }

    u64* y64 = reinterpret_cast<u64*>(y_sm);
    const u64* w64 = reinterpret_cast<const u64*>(w_sm);
    const int srow0 = (r0 >> 3) & 7;
    const int srow1 = (r1 >> 3) & 7;

#pragma unroll 1
    for (int ch = 0; ch < KDIM / KC; ch++) {
        __syncthreads();
        // store prefetched chunk, swizzled
#pragma unroll
        for (int rr = 0; rr < 2; rr++) {
            int row = rr ? r1 : r0;
            int s = rr ? srow1 : srow0;
#pragma unroll
            for (int j = 0; j < 4; j++) {
                float4 vv = pre[rr][j];
                y64[row * 8 + ((2 * j) ^ s)]     = pack2(vv.x, vv.y);
                y64[row * 8 + ((2 * j + 1) ^ s)] = pack2(vv.z, vv.w);
            }
        }
        __syncthreads();

        // prefetch next chunk (latency hidden under FMA loop)
        if (ch + 1 < KDIM / KC) {
            int k0 = (ch + 1) * KC;
#pragma unroll
            for (int rr = 0; rr < 2; rr++) {
                int grow = row0 + (rr ? r1 : r0);
                if (grow < NNODES) {
                    const float4* src = reinterpret_cast<const float4*>(
                        Y + (size_t)grow * KDIM + k0);
#pragma unroll
                    for (int j = 0; j < 4; j++) pre[rr][j] = src[j];
                } else {
#pragma unroll
                    for (int j = 0; j < 4; j++) pre[rr][j] = make_float4(0, 0, 0, 0);
                }
            }
        }

        const int pg0 = ch * 8;   // global pair base
#pragma unroll
        for (int p = 0; p < 8; p++) {
            u64 yk[8], wk[8];
            const int ppy = p ^ (rg & 7);
            const int ppw = (pg0 + p) ^ cg;
#pragma unroll
            for (int i = 0; i < 8; i++)
                yk[i] = y64[(rg * 8 + i) * 8 + ppy];
#pragma unroll
            for (int j = 0; j < 8; j++)
                wk[j] = w64[(cg * 8 + j) * (KDIM / 2) + ppw];
#pragma unroll
            for (int i = 0; i < 8; i++)
#pragma unroll
                for (int j = 0; j < 8; j++)
                    FMA_F32X2(acc[i * 8 + j], yk[i], wk[j]);
        }
    }

    // epilogue
    float bs[8];
#pragma unroll
    for (int j = 0; j < 8; j++) bs[j] = bias[cg * 8 + j];

#pragma unroll
    for (int i = 0; i < 8; i++) {
        int grow = row0 + rg * 8 + i;
        if (grow < NNODES) {
            float4 oa, ob;
            oa.x = fmaxf(hsum(acc[i * 8 + 0]) + bs[0], 0.f);
            oa.y = fmaxf(hsum(acc[i * 8 + 1]) + bs[1], 0.f);
            oa.z = fmaxf(hsum(acc[i * 8 + 2]) + bs[2], 0.f);
            oa.w = fmaxf(hsum(acc[i * 8 + 3]) + bs[3], 0.f);
            ob.x = fmaxf(hsum(acc[i * 8 + 4]) + bs[4], 0.f);
            ob.y = fmaxf(hsum(acc[i * 8 + 5]) + bs[5], 0.f);
            ob.z = fmaxf(hsum(acc[i * 8 + 6]) + bs[6], 0.f);
            ob.w = fmaxf(hsum(acc[i * 8 + 7]) + bs[7], 0.f);
            float4* dst = reinterpret_cast<float4*>(out + (size_t)grow * OUT_ + cg * 8);
            dst[0] = oa;
            dst[1] = ob;
        }
    }
}

// ---------------------------------------------------------------------------
// Inputs (metadata order): x, W, u, c, b, adj
// ---------------------------------------------------------------------------
extern "C" void kernel_launch(void* const* d_in, const int* in_sizes, int n_in,
                              void* d_out, int out_size) {
    const float* x    = (const float*)d_in[0];
    const float* W    = (const float*)d_in[1];
    const float* u    = (const float*)d_in[2];
    const float* cvec = (const float*)d_in[3];
    const float* bias = (const float*)d_in[4];
    const int*   adj  = (const int*)d_in[5];
    float* out = (float*)d_out;

    float* yptr;
    cudaGetSymbolAddress((void**)&yptr, g_y);

    k_ux<<<(NNODES * 4 + 511) / 512, 512>>>(x, u, cvec);
    k_attn<<<NNODES / 8, 256>>>(x, adj);
    k_gemm<<<(NNODES + MT - 1) / MT, 64>>>(W, bias, yptr, out);
}

// round 4
// speedup vs baseline: 1.4299x; 1.3403x over previous
#include <cuda_runtime.h>

#define B_ 2
#define V_ 20000
#define C_ 32
#define NB_ 12
#define KS_ 9
#define OUT_ 32
#define NNODES (B_*V_)
#define KDIM (KS_*C_)     /* 288 */
#define MROWS 40064       /* NNODES padded to multiple of 128 */

typedef unsigned long long u64;

// Scratch (module-allocated)
__device__ float g_ep[NNODES * 12];              // exp(ux+c), padded to 12 (pads=0)
__device__ float g_em[NNODES * 12];              // exp(-ux),  padded to 12 (pads=0)
__device__ float g_y[(size_t)MROWS * KDIM];      // 46 MB (pad rows read, never written)

#define FMA_F32X2(d, a, b) \
    asm("fma.rn.f32x2 %0, %1, %2, %0;" : "+l"(d) : "l"(a), "l"(b))

__device__ __forceinline__ u64 pack2(float a, float b) {
    u64 r; asm("mov.b64 %0, {%1,%2};" : "=l"(r) : "f"(a), "f"(b)); return r;
}
__device__ __forceinline__ float lo32(u64 v) {
    float a, b; asm("mov.b64 {%0,%1}, %2;" : "=f"(a), "=f"(b) : "l"(v)); return a;
}
__device__ __forceinline__ float hi32(u64 v) {
    float a, b; asm("mov.b64 {%0,%1}, %2;" : "=f"(a), "=f"(b) : "l"(v)); return b;
}
__device__ __forceinline__ float hsum(u64 v) { return lo32(v) + hi32(v); }

// ---------------------------------------------------------------------------
// Kernel 1: ux = x.u ; store E+[k]=exp(ux+c), E-[k]=exp(-ux), 12-padded.
// 4 threads per node, butterfly reduce, float4 stores.
// ---------------------------------------------------------------------------
__global__ void __launch_bounds__(512) k_ux(const float* __restrict__ x,
                                            const float* __restrict__ u,
                                            const float* __restrict__ cvec) {
    __shared__ float u_sm[C_ * KS_];
    __shared__ float c_sm[KS_];
    for (int i = threadIdx.x; i < C_ * KS_; i += 512) u_sm[i] = u[i];
    if (threadIdx.x < KS_) c_sm[threadIdx.x] = cvec[threadIdx.x];
    __syncthreads();

    int t = blockIdx.x * 512 + threadIdx.x;
    int node = t >> 2;
    int qq = t & 3;
    bool valid = node < NNODES;
    int nc = valid ? node : (NNODES - 1);

    const float4* xr = reinterpret_cast<const float4*>(x + (size_t)nc * C_) + qq * 2;
    float4 v0 = xr[0];
    float4 v1 = xr[1];
    float xs[8] = {v0.x, v0.y, v0.z, v0.w, v1.x, v1.y, v1.z, v1.w};

    float acc[KS_];
#pragma unroll
    for (int k = 0; k < KS_; k++) acc[k] = 0.f;
    const int cbase = qq * 8;
#pragma unroll
    for (int j = 0; j < 8; j++)
#pragma unroll
        for (int k = 0; k < KS_; k++)
            acc[k] = fmaf(xs[j], u_sm[(cbase + j) * KS_ + k], acc[k]);
#pragma unroll
    for (int k = 0; k < KS_; k++) acc[k] += __shfl_xor_sync(0xffffffffu, acc[k], 1);
#pragma unroll
    for (int k = 0; k < KS_; k++) acc[k] += __shfl_xor_sync(0xffffffffu, acc[k], 2);

    // all 4 threads now hold the full acc[0..8]; thread qq<3 stores float4 part qq
    if (valid && qq < 3) {
        float4 pe, me;
        if (qq < 2) {
            int kb = qq * 4;
            pe = make_float4(__expf(acc[kb] + c_sm[kb]),
                             __expf(acc[kb + 1] + c_sm[kb + 1]),
                             __expf(acc[kb + 2] + c_sm[kb + 2]),
                             __expf(acc[kb + 3] + c_sm[kb + 3]));
            me = make_float4(__expf(-acc[kb]), __expf(-acc[kb + 1]),
                             __expf(-acc[kb + 2]), __expf(-acc[kb + 3]));
        } else {
            pe = make_float4(__expf(acc[8] + c_sm[8]), 0.f, 0.f, 0.f);
            me = make_float4(__expf(-acc[8]), 0.f, 0.f, 0.f);
        }
        reinterpret_cast<float4*>(g_ep + (size_t)node * 12)[qq] = pe;
        reinterpret_cast<float4*>(g_em + (size_t)node * 12)[qq] = me;
    }
}

// ---------------------------------------------------------------------------
// Kernel 2: exp-free attention + neighbor aggregation -> g_y[node][288]
// Warp per node. q[n][k] = E+self[k]*E-nb[k], normalized, inv_deg folded.
// ---------------------------------------------------------------------------
__global__ void __launch_bounds__(256) k_attn(const float* __restrict__ x,
                                              const int* __restrict__ adj) {
    __shared__ float q_sm[8][NB_ * 12];
    const int warp = threadIdx.x >> 5;
    const int lane = threadIdx.x & 31;
    const int node = blockIdx.x * 8 + warp;   // grid = 5000 exact
    const int b = node / V_;
    const int v = node - b * V_;

    int a = (lane < NB_) ? adj[v * NB_ + lane] : 0;
    unsigned nz = __ballot_sync(0xffffffffu, a != 0);
    int deg = __popc(nz);
    float inv_deg = deg ? (1.f / (float)deg) : 0.f;

    if (a) {
        const float4* em4 = reinterpret_cast<const float4*>(
            g_em + (size_t)(b * V_ + (a - 1)) * 12);
        const float4* ep4 = reinterpret_cast<const float4*>(
            g_ep + (size_t)node * 12);
        float4 m0 = em4[0], m1 = em4[1], m2 = em4[2];
        float4 p0 = ep4[0], p1 = ep4[1], p2 = ep4[2];
        float q0 = p0.x * m0.x, q1 = p0.y * m0.y, q2 = p0.z * m0.z, q3 = p0.w * m0.w;
        float q4 = p1.x * m1.x, q5 = p1.y * m1.y, q6 = p1.z * m1.z, q7 = p1.w * m1.w;
        float q8 = p2.x * m2.x;
        float s = q0 + q1 + q2 + q3 + q4 + q5 + q6 + q7 + q8;
        float sc = inv_deg / s;
        float4* qr = reinterpret_cast<float4*>(&q_sm[warp][lane * 12]);
        qr[0] = make_float4(q0 * sc, q1 * sc, q2 * sc, q3 * sc);
        qr[1] = make_float4(q4 * sc, q5 * sc, q6 * sc, q7 * sc);
        qr[2] = make_float4(q8 * sc, 0.f, 0.f, 0.f);
    }
    __syncwarp();

    u64 acc[5];
#pragma unroll
    for (int t = 0; t < 5; t++) acc[t] = 0ull;

#pragma unroll
    for (int n = 0; n < NB_; n++) {
        int an = __shfl_sync(0xffffffffu, a, n);
        if (an == 0) continue;   // warp-uniform
        float xv = x[((size_t)b * V_ + (an - 1)) * C_ + lane];
        u64 xx = pack2(xv, xv);
        const u64* q64 = reinterpret_cast<const u64*>(&q_sm[warp][n * 12]);
#pragma unroll
        for (int t = 0; t < 5; t++) FMA_F32X2(acc[t], q64[t], xx);
    }

    float* yo = g_y + (size_t)node * KDIM;
#pragma unroll
    for (int t = 0; t < 4; t++) {
        yo[(2 * t) * C_ + lane] = lo32(acc[t]);
        yo[(2 * t + 1) * C_ + lane] = hi32(acc[t]);
    }
    yo[8 * C_ + lane] = lo32(acc[4]);
}

// ---------------------------------------------------------------------------
// Kernel 3: out = relu(Y @ W2 + b). M=40000(pad 40064), K=288, N=32.
// 128 threads, MT=128 rows, 4x8 microtile, warp-uniform cols, f32x2 FMAs.
// y staged transposed [kpair][row] in smem; W transposed [kpair][o] (broadcast).
// ---------------------------------------------------------------------------
#define MT 128
#define NCH (KDIM / 16)   /* 18 chunks of 16 floats (8 k-pairs) */

__global__ void __launch_bounds__(128) k_gemm(const float* __restrict__ W,
                                              const float* __restrict__ bias,
                                              const float* __restrict__ Y,
                                              float* __restrict__ out) {
    __shared__ __align__(16) u64 wt_sm[(KDIM / 2) * OUT_];  // [kp][o], 36 KB
    __shared__ __align__(16) u64 yt_sm[8 * MT];             // [kp_local][row], 8 KB

    const int tid = threadIdx.x;
    const int cg = tid >> 5;     // warp id -> output cols cg*8..cg*8+7 (warp-uniform)
    const int lane = tid & 31;

    // Stage W transposed+paired: wt[kp][o] = (W2[2kp][o], W2[2kp+1][o])
    // W2[ks*32+c][o] = W[c*288 + ks*32 + o]; pair = (c, c+1) within same ks.
    for (int idx = tid; idx < (KDIM / 2) * OUT_; idx += 128) {
        int i2 = idx >> 5;        // k-pair index
        int o = idx & 31;
        int k0 = 2 * i2;
        int c = k0 & 31, ks = k0 >> 5;
        const float* wp = W + c * KDIM + ks * OUT_ + o;
        wt_sm[idx] = pack2(wp[0], wp[KDIM]);
    }

    const int row0 = blockIdx.x * MT;

    u64 acc[4][8];
#pragma unroll
    for (int i = 0; i < 4; i++)
#pragma unroll
        for (int j = 0; j < 8; j++) acc[i][j] = 0ull;

    // prefetch chunk 0 (each thread owns row row0+tid; pad rows exist in g_y)
    const float4* ysrc = reinterpret_cast<const float4*>(Y + (size_t)(row0 + tid) * KDIM);
    float4 pre[4];
#pragma unroll
    for (int j = 0; j < 4; j++) pre[j] = ysrc[j];

#pragma unroll 1
    for (int ch = 0; ch < NCH; ch++) {
        __syncthreads();
        // transposed store: yt[2j / 2j+1][tid]
#pragma unroll
        for (int j = 0; j < 4; j++) {
            yt_sm[(2 * j) * MT + tid]     = pack2(pre[j].x, pre[j].y);
            yt_sm[(2 * j + 1) * MT + tid] = pack2(pre[j].z, pre[j].w);
        }
        __syncthreads();

        if (ch + 1 < NCH) {
#pragma unroll
            for (int j = 0; j < 4; j++) pre[j] = ysrc[(ch + 1) * 4 + j];
        }

        const u64* wrow = &wt_sm[(size_t)ch * 8 * OUT_ + cg * 8];
#pragma unroll
        for (int kp = 0; kp < 8; kp++) {
            u64 yk[4];
#pragma unroll
            for (int i = 0; i < 4; i++) yk[i] = yt_sm[kp * MT + lane + 32 * i];
            u64 wk[8];
#pragma unroll
            for (int j = 0; j < 8; j++) wk[j] = wrow[kp * OUT_ + j];
#pragma unroll
            for (int i = 0; i < 4; i++)
#pragma unroll
                for (int j = 0; j < 8; j++)
                    FMA_F32X2(acc[i][j], yk[i], wk[j]);
        }
    }

    // epilogue: bias + relu + store (rows lane+32i)
    float bs[8];
#pragma unroll
    for (int j = 0; j < 8; j++) bs[j] = bias[cg * 8 + j];

#pragma unroll
    for (int i = 0; i < 4; i++) {
        int grow = row0 + lane + 32 * i;
        if (grow < NNODES) {
            float4 oa, ob;
            oa.x = fmaxf(hsum(acc[i][0]) + bs[0], 0.f);
            oa.y = fmaxf(hsum(acc[i][1]) + bs[1], 0.f);
            oa.z = fmaxf(hsum(acc[i][2]) + bs[2], 0.f);
            oa.w = fmaxf(hsum(acc[i][3]) + bs[3], 0.f);
            ob.x = fmaxf(hsum(acc[i][4]) + bs[4], 0.f);
            ob.y = fmaxf(hsum(acc[i][5]) + bs[5], 0.f);
            ob.z = fmaxf(hsum(acc[i][6]) + bs[6], 0.f);
            ob.w = fmaxf(hsum(acc[i][7]) + bs[7], 0.f);
            float4* dst = reinterpret_cast<float4*>(out + (size_t)grow * OUT_ + cg * 8);
            dst[0] = oa;
            dst[1] = ob;
        }
    }
}

// ---------------------------------------------------------------------------
// Inputs (metadata order): x, W, u, c, b, adj
// ---------------------------------------------------------------------------
extern "C" void kernel_launch(void* const* d_in, const int* in_sizes, int n_in,
                              void* d_out, int out_size) {
    const float* x    = (const float*)d_in[0];
    const float* W    = (const float*)d_in[1];
    const float* u    = (const float*)d_in[2];
    const float* cvec = (const float*)d_in[3];
    const float* bias = (const float*)d_in[4];
    const int*   adj  = (const int*)d_in[5];
    float* out = (float*)d_out;

    float* yptr;
    cudaGetSymbolAddress((void**)&yptr, g_y);

    k_ux<<<(NNODES * 4 + 511) / 512, 512>>>(x, u, cvec);
    k_attn<<<NNODES / 8, 256>>>(x, adj);
    k_gemm<<<MROWS / MT, 128>>>(W, bias, yptr, out);
}